// round 4
// baseline (speedup 1.0000x reference)
#include <cuda_runtime.h>

// TreeNLLLoss, two launches per replay:
//   1) pack_labels: labels int32 (4 MB) -> uint8 (1 MB)  [values are 0..15]
//   2) fused gather+reduce with last-block finalize
//
//   loss = sum_e edge_pot[e, 16*tc+tp] + sum_e unary[child_e, tc] + unary[root, l_root]
//   out  = -(loss - partition)
// E = 1,000,000 edges, N = 1,000,001 nodes, C = 16.

#define C 16
#define EPT 4
#define THREADS 256
#define MAX_BLOCKS 4096
#define N_MAX 1000704   // >= 1,000,001, padded

__device__ unsigned char g_labels8[N_MAX];
__device__ float         g_partials[MAX_BLOCKS];
__device__ unsigned      g_count = 0;   // returns to 0 each replay (last block resets)

// ── pre-pass: pack labels to uint8 ──
__global__ void __launch_bounds__(THREADS)
pack_labels(const int* __restrict__ labels, int N)
{
    int t = blockIdx.x * THREADS + threadIdx.x;   // each thread packs 4 labels
    int base = t * 4;
    if (base + 4 <= N) {
        int4 l = __ldg((const int4*)labels + t);
        uchar4 u = make_uchar4((unsigned char)l.x, (unsigned char)l.y,
                               (unsigned char)l.z, (unsigned char)l.w);
        *((uchar4*)(g_labels8 + base)) = u;
    } else {
        for (int i = base; i < N; i++)
            g_labels8[i] = (unsigned char)__ldg(&labels[i]);
    }
}

// ── main: gather + reduce ──
__global__ void __launch_bounds__(THREADS)
fused_kernel(const float* __restrict__ edge_pot,
             const float* __restrict__ unary,
             const int*   __restrict__ labels,
             const int*   __restrict__ child_idx,
             const int*   __restrict__ parent_idx,
             const int*   __restrict__ root_idx,
             const float* __restrict__ partition,
             float* __restrict__ out,
             int E)
{
    const int tid  = blockIdx.x * THREADS + threadIdx.x;
    const int base = tid * EPT;

    float s = 0.0f;

    if (base + EPT <= E) {
        // Level 0: coalesced int4 index loads
        int4 c4 = __ldg((const int4*)child_idx  + tid);
        int4 p4 = __ldg((const int4*)parent_idx + tid);
        int c[EPT] = {c4.x, c4.y, c4.z, c4.w};
        int p[EPT] = {p4.x, p4.y, p4.z, p4.w};

        // Level 1: packed-label gathers (1 MB array, L2-resident, MLP=8)
        int tc[EPT], tp[EPT];
        #pragma unroll
        for (int j = 0; j < EPT; j++) {
            tc[j] = (int)__ldg(&g_labels8[c[j]]);
            tp[j] = (int)__ldg(&g_labels8[p[j]]);
        }

        // Level 2: potential gathers (MLP=8)
        //   edge_pot: one-shot lines -> streaming/evict-first
        //   unary:    reusable across replays -> default caching
        float ep[EPT], cu[EPT];
        #pragma unroll
        for (int j = 0; j < EPT; j++) {
            ep[j] = __ldcs(&edge_pot[(size_t)(base + j) * (C * C) + tc[j] * C + tp[j]]);
            cu[j] = __ldg(&unary[(size_t)c[j] * C + tc[j]]);
        }

        #pragma unroll
        for (int j = 0; j < EPT; j++) s += ep[j] + cu[j];
    } else {
        for (int j = 0; j < EPT; j++) {
            int e = base + j;
            if (e < E) {
                int ci = __ldg(&child_idx[e]);
                int pi = __ldg(&parent_idx[e]);
                int tc = (int)__ldg(&g_labels8[ci]);
                int tp = (int)__ldg(&g_labels8[pi]);
                s += __ldcs(&edge_pot[(size_t)e * (C * C) + tc * C + tp]);
                s += __ldg(&unary[(size_t)ci * C + tc]);
            }
        }
    }

    // ── block reduce ──
    #pragma unroll
    for (int off = 16; off > 0; off >>= 1)
        s += __shfl_down_sync(0xffffffffu, s, off);

    __shared__ float warp_sums[THREADS / 32];
    const int lane = threadIdx.x & 31;
    const int wid  = threadIdx.x >> 5;
    if (lane == 0) warp_sums[wid] = s;
    __syncthreads();

    if (wid == 0) {
        float t = (lane < THREADS / 32) ? warp_sums[lane] : 0.0f;
        #pragma unroll
        for (int off = 4; off > 0; off >>= 1)
            t += __shfl_down_sync(0xffffffffu, t, off);
        if (lane == 0) g_partials[blockIdx.x] = t;
    }

    // ── last-block-done finalize ──
    __shared__ bool is_last;
    __threadfence();
    if (threadIdx.x == 0) {
        unsigned ticket = atomicAdd(&g_count, 1u);
        is_last = (ticket == gridDim.x - 1);
    }
    __syncthreads();

    if (is_last) {
        double acc = 0.0;
        for (int i = threadIdx.x; i < (int)gridDim.x; i += THREADS)
            acc += (double)__ldcg(&g_partials[i]);

        #pragma unroll
        for (int off = 16; off > 0; off >>= 1)
            acc += __shfl_down_sync(0xffffffffu, acc, off);

        __shared__ double dwarp[THREADS / 32];
        if (lane == 0) dwarp[wid] = acc;
        __syncthreads();

        if (wid == 0) {
            double t = (lane < THREADS / 32) ? dwarp[lane] : 0.0;
            #pragma unroll
            for (int off = 4; off > 0; off >>= 1)
                t += __shfl_down_sync(0xffffffffu, t, off);
            if (lane == 0) {
                int r = __ldg(root_idx);
                float root_unary = __ldg(&unary[(size_t)r * C + (int)g_labels8[r]]);
                double loss = t + (double)root_unary;
                out[0] = -(float)(loss - (double)__ldg(partition));
                g_count = 0;   // reset for next replay
            }
        }
    }
}

extern "C" void kernel_launch(void* const* d_in, const int* in_sizes, int n_in,
                              void* d_out, int out_size)
{
    const float* edge_pot   = (const float*)d_in[0];
    const float* unary      = (const float*)d_in[1];
    const int*   labels     = (const int*)d_in[2];
    const int*   child_idx  = (const int*)d_in[3];
    const int*   parent_idx = (const int*)d_in[4];
    const int*   root_idx   = (const int*)d_in[5];
    const float* partition  = (const float*)d_in[6];
    float* out = (float*)d_out;

    int N = in_sizes[2];
    int E = in_sizes[3];

    int pack_blocks = (N + THREADS * 4 - 1) / (THREADS * 4);
    pack_labels<<<pack_blocks, THREADS>>>(labels, N);

    int per_block = THREADS * EPT;
    int blocks = (E + per_block - 1) / per_block;
    if (blocks > MAX_BLOCKS) blocks = MAX_BLOCKS;  // E=1e6 -> 977

    fused_kernel<<<blocks, THREADS>>>(edge_pot, unary, labels, child_idx,
                                      parent_idx, root_idx, partition, out, E);
}